// round 17
// baseline (speedup 1.0000x reference)
#include <cuda_runtime.h>
#include <cuda_fp16.h>
#include <cstdint>

#define NB 256
#define NA 1024
#define NE 8192
#define NEP 11264          // max padded edges (each row padded to multiple of 4)
#define F1 64
#define FP 128
#define SLOPE 0.01f
#define TILE 256
#define NTILES (NA / TILE)

// ---------- device scratch (allocation-free: static globals) ----------
__device__ float g_dinv[NA];
__device__ int   g_rowptr[NA + 1];     // padded-CSR rowptr (multiples of 4); [NA] = NE_P
__device__ int   g_edgeoff[NEP];       // per-edge byte offset: src<<7 (zero-row pad = 1024<<7)

__device__ __forceinline__ float leaky(float v) {
    return v >= 0.0f ? v : SLOPE * v;
}

__device__ __forceinline__ unsigned smem_u32(const void* p) {
    return (unsigned)__cvta_generic_to_shared(p);
}
__device__ __forceinline__ void ldsm_x4(unsigned addr, unsigned& r0, unsigned& r1,
                                        unsigned& r2, unsigned& r3) {
    asm volatile("ldmatrix.sync.aligned.m8n8.x4.shared.b16 {%0,%1,%2,%3}, [%4];"
                 : "=r"(r0), "=r"(r1), "=r"(r2), "=r"(r3) : "r"(addr));
}
__device__ __forceinline__ void ldsm_x4t(unsigned addr, unsigned& r0, unsigned& r1,
                                         unsigned& r2, unsigned& r3) {
    asm volatile("ldmatrix.sync.aligned.m8n8.x4.trans.shared.b16 {%0,%1,%2,%3}, [%4];"
                 : "=r"(r0), "=r"(r1), "=r"(r2), "=r"(r3) : "r"(addr));
}
__device__ __forceinline__ void mma16816(float* c, unsigned a0, unsigned a1,
                                         unsigned a2, unsigned a3,
                                         unsigned b0, unsigned b1) {
    asm volatile(
        "mma.sync.aligned.m16n8k16.row.col.f32.f16.f16.f32 "
        "{%0,%1,%2,%3}, {%4,%5,%6,%7}, {%8,%9}, {%0,%1,%2,%3};"
        : "+f"(c[0]), "+f"(c[1]), "+f"(c[2]), "+f"(c[3])
        : "r"(a0), "r"(a1), "r"(a2), "r"(a3), "r"(b0), "r"(b1));
}

// ---------- K0: degrees, dinv, quad-padded CSR with byte offsets ----------
__global__ void k_setup(const unsigned int* __restrict__ ei_raw) {
    __shared__ int scnt[NA];
    __shared__ int scur[NA];
    __shared__ int srow[NA];
    __shared__ int warpsum[32];
    __shared__ int s_is64;
    int tid = threadIdx.x, lane = tid & 31, wid = tid >> 5;

    if (tid < 32) {   // int64 edge_index has zero high words (values < 1024)
        unsigned m = __ballot_sync(0xffffffffu, ei_raw[2 * tid + 1] != 0u);
        if (tid == 0) s_is64 = (m == 0u);
    }
    scnt[tid] = 0;
    __syncthreads();
    const int is64 = s_is64;

    for (int e = tid; e < NE; e += NA) {
        int d = is64 ? (int)ei_raw[2 * (NE + e)] : (int)ei_raw[NE + e];
        atomicAdd(&scnt[d], 1);
    }
    __syncthreads();

    int my = scnt[tid];
    g_dinv[tid] = rsqrtf((float)(my + 1));   // deg = 1 + REAL in-degree (self loop)

    int plen = (my + 3) & ~3;                // padded row length (multiple of 4)

    // warp-shfl inclusive scan of padded lengths
    int v = plen;
#pragma unroll
    for (int o = 1; o < 32; o <<= 1) {
        int t = __shfl_up_sync(0xffffffffu, v, o);
        if (lane >= o) v += t;
    }
    if (lane == 31) warpsum[wid] = v;
    __syncthreads();
    if (wid == 0) {
        int w = warpsum[lane];
#pragma unroll
        for (int o = 1; o < 32; o <<= 1) {
            int t = __shfl_up_sync(0xffffffffu, w, o);
            if (lane >= o) w += t;
        }
        warpsum[lane] = w;
    }
    __syncthreads();
    int tot  = warpsum[31];
    int excl = v + (wid > 0 ? warpsum[wid - 1] : 0) - plen;
    scur[tid]     = excl;
    srow[tid]     = excl;
    g_rowptr[tid] = excl;
    if (tid == 0) g_rowptr[NA] = tot;
    __syncthreads();

    // scatter real edges as byte offsets (src<<7)
    for (int e = tid; e < NE; e += NA) {
        int s = is64 ? (int)ei_raw[2 * e]        : (int)ei_raw[e];
        int d = is64 ? (int)ei_raw[2 * (NE + e)] : (int)ei_raw[NE + e];
        int pos = atomicAdd(&scur[d], 1);
        g_edgeoff[pos] = s << 7;
    }
    __syncthreads();

    // fill padding slots with the zero row (atom NA)
    int fill_end = (tid == NA - 1) ? tot : srow[tid + 1];
    for (int p = scur[tid]; p < fill_end; p++) g_edgeoff[p] = NA << 7;
}

// ---------- K1: whole network per molecule, 1024 threads ----------
#define AGG_PITCH 72   // halfs; ldmatrix conflict-free
#define SH1_HALFS ((NA + 1) * F1)                  // 65600 halfs (incl. zero row)
#define SW2_OFF   SH1_HALFS
#define SAGG_OFF  (SW2_OFF + F1 * AGG_PITCH)       // + 4608
#define SEDGE_OFF (SAGG_OFF + TILE * AGG_PITCH)    // + 18432 halfs
#define SMEM_MOL_BYTES (SEDGE_OFF * 2 + NEP * 4)   // 177280 + 45056 = 222336 B
// static __shared__ kept under ~9.3 KB so static+dynamic fits the 227 KB cap;
// pool/gs alias the sagg region (dead after the last tile's final sync)

__global__ void __launch_bounds__(1024, 1)
k_mol(const float* __restrict__ x,
      const float* __restrict__ W1, const float* __restrict__ b1,
      const float* __restrict__ W2, const float* __restrict__ b2,
      const float* __restrict__ Wp, const float* __restrict__ bp,
      float* __restrict__ outp) {
    extern __shared__ __half smh[];
    __half* sh1   = smh;                           // [1025][64] fp16, pre-scaled by dinv
    __half* sW2h  = smh + SW2_OFF;
    __half* sagg  = smh + SAGG_OFF;
    int*    sedge = (int*)(smh + SEDGE_OFF);       // quad-padded edge byte-offsets
    float*  sx4   = (float*)(smh + SAGG_OFF);      // [1025][4] x', aliases sagg (dead before use)
    float*  pool  = (float*)(smh + SAGG_OFF);      // [32][32], aliases sagg (used after last tile)
    float*  gs    = pool + 32 * 32;                // [64], same region
    __shared__ float sW1[3 * F1];
    __shared__ float sb1[F1];
    __shared__ float sdinv[NA];
    __shared__ int   srow[NA + 1];

    int b = blockIdx.x;
    int tid = threadIdx.x, wid = tid >> 5, lane = tid & 31;

    // stage rowptr, dinv, W1, b1, W2(fp16), edges, x' (dinv-prescaled, float4 rows)
    srow[tid] = g_rowptr[tid];
    if (tid == 0) srow[NA] = g_rowptr[NA];
    float f = g_dinv[tid];
    sdinv[tid] = f;
    if (tid < 3 * F1) sW1[tid] = W1[tid];
    if (tid < F1)     sb1[tid] = b1[tid];
    for (int t = tid; t < F1 * F1; t += 1024) {
        int k = t >> 6, j = t & 63;
        sW2h[k * AGG_PITCH + j] = __float2half_rn(W2[t]);
    }
#pragma unroll
    for (int t = tid; t < NEP; t += 1024) sedge[t] = g_edgeoff[t];
    {
        const float* xb = x + (size_t)b * (NA * 3);
        sx4[4 * tid + 0] = f * xb[3 * tid + 0];
        sx4[4 * tid + 1] = f * xb[3 * tid + 1];
        sx4[4 * tid + 2] = f * xb[3 * tid + 2];
        if (tid < 4)  sx4[4 * NA + tid] = 0.0f;            // zero x row
        if (tid < 32) ((unsigned*)(sh1 + NA * F1))[tid] = 0u;  // zero h1 row
    }
    __syncthreads();

    // ---- Layer 1: thread = atom; quad-processed gather; h1' = dinv*leaky(agg@W1+b1) ----
    {
        const char* sx4c = (const char*)sx4;
        float a0 = sx4[4 * tid + 0], a1 = sx4[4 * tid + 1], a2 = sx4[4 * tid + 2];
        float c0 = 0.0f, c1 = 0.0f, c2 = 0.0f;
        int r0 = srow[tid], r1 = srow[tid + 1];
        for (int e = r0; e < r1; e += 4) {
            int4 off = *(const int4*)(sedge + e);          // 4 edges per LDS.128
            float4 v0 = *(const float4*)(sx4c + (off.x >> 3));
            float4 v1 = *(const float4*)(sx4c + (off.y >> 3));
            float4 v2 = *(const float4*)(sx4c + (off.z >> 3));
            float4 v3 = *(const float4*)(sx4c + (off.w >> 3));
            a0 += v0.x; a1 += v0.y; a2 += v0.z;
            c0 += v1.x; c1 += v1.y; c2 += v1.z;
            a0 += v2.x; a1 += v2.y; a2 += v2.z;
            c0 += v3.x; c1 += v3.y; c2 += v3.z;
        }
        a0 = (a0 + c0) * f; a1 = (a1 + c1) * f; a2 = (a2 + c2) * f;

        // in-warp transpose: lane l writes features 2l,2l+1 (scaled by dinv_q)
        int j2 = 2 * lane;
        int rowbase = tid & ~31;
#pragma unroll 4
        for (int q = 0; q < 32; q++) {
            float q0 = __shfl_sync(0xffffffffu, a0, q);
            float q1 = __shfl_sync(0xffffffffu, a1, q);
            float q2 = __shfl_sync(0xffffffffu, a2, q);
            float fq = __shfl_sync(0xffffffffu, f,  q);
            float v0 = q0 * sW1[j2]     + q1 * sW1[F1 + j2]     + q2 * sW1[2 * F1 + j2]     + sb1[j2];
            float v1 = q0 * sW1[j2 + 1] + q1 * sW1[F1 + j2 + 1] + q2 * sW1[2 * F1 + j2 + 1] + sb1[j2 + 1];
            ((__half2*)&sh1[(size_t)(rowbase + q) * F1])[lane] =
                __floats2half2_rn(fq * leaky(v0), fq * leaky(v1));
        }
    }
    __syncthreads();   // sh1 complete; sx4 dead (sagg may now be overwritten)

    // ---- Layer 2 tiles: offset-direct quad gather + HMMA + pool ----
    const char* sh1c = (const char*)sh1 + lane * 4;   // lane's half2 within any row
    unsigned sagg_b = smem_u32(sagg);
    unsigned sw2_b  = smem_u32(sW2h);
    int m0 = (wid >> 1) * 16;
    int j0 = (wid & 1) * 32;
    int grp = lane >> 3, lr = lane & 7;
    int t4 = lane & 3;

    float pacc[4][2];
#pragma unroll
    for (int nt = 0; nt < 4; nt++) pacc[nt][0] = pacc[nt][1] = 0.0f;

    for (int tile = 0; tile < NTILES; tile++) {
        int base = tile * TILE;

        // Phase A: warp-per-atom quad gather; 4 independent accumulator chains
        for (int a = wid; a < TILE; a += 32) {
            int atom = base + a;
            __half2 acc0 = *(const __half2*)(sh1c + (atom << 7));   // self term
            __half2 acc1 = __float2half2_rn(0.0f);
            __half2 acc2 = __float2half2_rn(0.0f);
            __half2 acc3 = __float2half2_rn(0.0f);
            int r0 = srow[atom], r1 = srow[atom + 1];
            for (int e = r0; e < r1; e += 4) {
                int4 off = *(const int4*)(sedge + e);               // 4 edges per LDS.128
                acc0 = __hadd2(acc0, *(const __half2*)(sh1c + off.x));
                acc1 = __hadd2(acc1, *(const __half2*)(sh1c + off.y));
                acc2 = __hadd2(acc2, *(const __half2*)(sh1c + off.z));
                acc3 = __hadd2(acc3, *(const __half2*)(sh1c + off.w));
            }
            __half2 d2 = __float2half2_rn(sdinv[atom]);
            acc0 = __hadd2(__hadd2(acc0, acc1), __hadd2(acc2, acc3));
            ((__half2*)&sagg[a * AGG_PITCH])[lane] = __hmul2(d2, acc0);
        }
        __syncthreads();

        // Phase B: 256x64x64 HMMA; warp tile m16 x n32
        float c[4][4];
#pragma unroll
        for (int q = 0; q < 4; q++)
#pragma unroll
            for (int r = 0; r < 4; r++) c[q][r] = 0.0f;

#pragma unroll
        for (int kc = 0; kc < F1; kc += 16) {
            int arow = m0 + (grp & 1) * 8 + lr;
            int acol = kc + (grp >> 1) * 8;
            unsigned a0, a1, a2, a3;
            ldsm_x4(sagg_b + (arow * AGG_PITCH + acol) * 2, a0, a1, a2, a3);

            int brow = kc + (grp & 1) * 8 + lr;
#pragma unroll
            for (int p = 0; p < 2; p++) {
                int bcol = j0 + p * 16 + (grp >> 1) * 8;
                unsigned b0, b1, b2r, b3;
                ldsm_x4t(sw2_b + (brow * AGG_PITCH + bcol) * 2, b0, b1, b2r, b3);
                mma16816(c[2 * p],     a0, a1, a2, a3, b0,  b1);
                mma16816(c[2 * p + 1], a0, a1, a2, a3, b2r, b3);
            }
        }

        // bias + leaky + shfl pool-reduce; accumulate in registers across tiles
#pragma unroll
        for (int nt = 0; nt < 4; nt++) {
            int jb = j0 + nt * 8 + 2 * t4;
            float bb0 = __ldg(&b2[jb]), bb1 = __ldg(&b2[jb + 1]);
            float s0 = leaky(c[nt][0] + bb0) + leaky(c[nt][2] + bb0);
            float s1 = leaky(c[nt][1] + bb1) + leaky(c[nt][3] + bb1);
#pragma unroll
            for (int o = 4; o < 32; o <<= 1) {
                s0 += __shfl_xor_sync(0xffffffffu, s0, o);
                s1 += __shfl_xor_sync(0xffffffffu, s1, o);
            }
            pacc[nt][0] += s0;
            pacc[nt][1] += s1;
        }
        __syncthreads();   // sagg consumed; safe to overwrite next tile (or pool below)
    }

    // ---- write pool partials once (into sagg alias — now dead), combine, mean, project ----
    if (lane < 4) {
#pragma unroll
        for (int nt = 0; nt < 4; nt++) {
            pool[wid * 32 + nt * 8 + 2 * t4]     = pacc[nt][0];
            pool[wid * 32 + nt * 8 + 2 * t4 + 1] = pacc[nt][1];
        }
    }
    __syncthreads();

    if (tid < F1) {
        int nh = tid >> 5, cw = tid & 31;
        float s = 0.0f;
#pragma unroll
        for (int m = 0; m < 16; m++) s += pool[(m * 2 + nh) * 32 + cw];
        gs[tid] = s * (1.0f / NA);
    }
    __syncthreads();

    if (tid < FP) {
        float v = bp[tid];
#pragma unroll
        for (int k = 0; k < F1; k++) v += gs[k] * Wp[k * FP + tid];
        outp[(size_t)b * FP + tid] = leaky(v);
    }
}

// ---------- launch ----------
extern "C" void kernel_launch(void* const* d_in, const int* in_sizes, int n_in,
                              void* d_out, int out_size) {
    const float* x        = (const float*)d_in[0];
    const unsigned int* e = (const unsigned int*)d_in[1];
    const float* W1       = (const float*)d_in[2];
    const float* b1       = (const float*)d_in[3];
    const float* W2       = (const float*)d_in[4];
    const float* b2       = (const float*)d_in[5];
    const float* Wp       = (const float*)d_in[6];
    const float* bp       = (const float*)d_in[7];
    float* out            = (float*)d_out;

    // idempotent host-side attribute set (capture-safe, no allocation)
    cudaFuncSetAttribute(k_mol, cudaFuncAttributeMaxDynamicSharedMemorySize,
                         SMEM_MOL_BYTES);

    k_setup<<<1, NA>>>(e);
    k_mol<<<NB, 1024, SMEM_MOL_BYTES>>>(x, W1, b1, W2, b2, Wp, bp, out);
}